// round 16
// baseline (speedup 1.0000x reference)
#include <cuda_runtime.h>
#include <cuda_fp16.h>
#include <cstdint>
#include <cstddef>

#define BATCH 64
#define HW    256
#define CH    1024
#define NTOK  256
#define TC    768
#define FD    512
#define MROWS (BATCH*HW)   // 16384

#define SCALE_F   256.0f
#define INV_SQ    (1.0f/65536.0f)

// ------------------------------ scratch (device globals; no allocs) ---------
__device__ __align__(256) __half g_wqh[(size_t)FD*CH],  g_wql[(size_t)FD*CH];
__device__ __align__(256) __half g_wkh[(size_t)FD*TC],  g_wkl[(size_t)FD*TC];
__device__ __align__(256) __half g_woh[(size_t)CH*CH],  g_wol[(size_t)CH*CH];   // Wo^T [f,c]
__device__ __align__(256) __half g_Qh[(size_t)MROWS*FD], g_Ql[(size_t)MROWS*FD];
__device__ __align__(256) __half g_Kh[(size_t)MROWS*FD], g_Kl[(size_t)MROWS*FD];
__device__ __align__(256) float  g_bvo[CH];
__device__ __align__(256) __half g_Wvoth[(size_t)CH*TC], g_Wvotl[(size_t)CH*TC];// (Wv@Wo)^T hi/lo
__device__ __align__(256) __half g_VWth[(size_t)MROWS*CH], g_VWtl[(size_t)MROWS*CH]; // [b][CH][NTOK]
__device__ __align__(256) float  g_S [(size_t)MROWS*NTOK];
__device__ __align__(256) __half g_bh[(size_t)MROWS*NTOK], g_bl[(size_t)MROWS*NTOK];

// ------------------------------ PTX helpers ---------------------------------
__device__ __forceinline__ uint32_t smem_u32(const void* p) {
    uint32_t a;
    asm("{ .reg .u64 t; cvta.to.shared.u64 t, %1; cvt.u32.u64 %0, t; }" : "=r"(a) : "l"(p));
    return a;
}
#define CP_ASYNC16(dst, src) \
    asm volatile("cp.async.cg.shared.global [%0], [%1], 16;" :: "r"(dst), "l"(src))
#define CP_COMMIT() asm volatile("cp.async.commit_group;" ::: "memory")
#define CP_WAIT1()  asm volatile("cp.async.wait_group 1;" ::: "memory")
#define CP_WAIT0()  asm volatile("cp.async.wait_group 0;" ::: "memory")

#define LDMX4(r, addr)                                                      \
    asm volatile("ldmatrix.sync.aligned.m8n8.x4.shared.b16 {%0,%1,%2,%3}, [%4];" \
        : "=r"((r)[0]), "=r"((r)[1]), "=r"((r)[2]), "=r"((r)[3]) : "r"(addr))

#define MMA16816(c, a, b)                                                   \
    asm volatile("mma.sync.aligned.m16n8k16.row.col.f32.f16.f16.f32 "       \
        "{%0,%1,%2,%3}, {%4,%5,%6,%7}, {%8,%9}, {%0,%1,%2,%3};"             \
        : "+f"((c)[0]), "+f"((c)[1]), "+f"((c)[2]), "+f"((c)[3])            \
        : "r"((a)[0]), "r"((a)[1]), "r"((a)[2]), "r"((a)[3]),               \
          "r"((b)[0]), "r"((b)[1]))

#define STS128(addr, r0, r1, r2, r3)                                        \
    asm volatile("st.shared.v4.b32 [%0], {%1,%2,%3,%4};"                    \
        :: "r"(addr), "r"(r0), "r"(r1), "r"(r2), "r"(r3) : "memory")

// split f -> fp16 hi/lo of (f*256), packed pairs
__device__ __forceinline__ void split2pack(float f0, float f1, uint32_t& hw, uint32_t& lw) {
    float s0 = f0 * SCALE_F, s1 = f1 * SCALE_F;
    __half h0 = __float2half_rn(s0);
    __half h1 = __float2half_rn(s1);
    __half l0 = __float2half_rn(s0 - __half2float(h0));
    __half l1 = __float2half_rn(s1 - __half2float(h1));
    hw = (uint32_t)__half_as_ushort(h0) | ((uint32_t)__half_as_ushort(h1) << 16);
    lw = (uint32_t)__half_as_ushort(l0) | ((uint32_t)__half_as_ushort(l1) << 16);
}

// ------------------------------ GEMM ----------------------------------------
// Operands are fp16 hi/lo splits of (X*256); accumulator holds 65536*true.
// TERMS==3: AhBh + AhBl + AlBh.   TERMS==1: AhBh only.
// CONVA: A read from fp32 source Af; LDG staged before kk-loop, converted with
//        split2pack and STS'd after it (hidden under HMMA).
// MODE 0: fp32 row-major C.  MODE 1: fp16 hi/lo row-major C.
// MODE 2: fp16 hi/lo TRANSPOSED C via smem; ldc = out pitch, sC = batch stride,
//         rbatch = source rows per batch.
#define STG_BYTES 32768
#define SMEM_BYTES (2*STG_BYTES)
#define SMEM_BYTES_T (128*129*4)

template <bool LO>
__device__ __forceinline__ void cp_tile2(
    const __half* __restrict__ gh, const __half* __restrict__ gl,
    int row0, int kof, int pitch, uint32_t sdst, int tid)
{
#pragma unroll
    for (int i = 0; i < 2; ++i) {
        int u = tid + i * 256;
        int row = u >> 2;
        int c4 = u & 3;
        {
            int c = c4;
            uint32_t dst = sdst + row * 128 + ((c ^ (row & 7)) << 4);
            const void* src = gh + (size_t)(row0 + row) * pitch + kof + c4 * 8;
            CP_ASYNC16(dst, src);
        }
        if (LO) {
            int c = c4 + 4;
            uint32_t dst = sdst + row * 128 + ((c ^ (row & 7)) << 4);
            const void* src = gl + (size_t)(row0 + row) * pitch + kof + c4 * 8;
            CP_ASYNC16(dst, src);
        }
    }
}

__device__ __forceinline__ void conv_ldg(
    const float* __restrict__ Af, int row0, int kof, int pitch,
    int tid, float4* st)
{
#pragma unroll
    for (int i = 0; i < 2; ++i) {
        int u = tid + i * 256;
        int row = u >> 2;
        int c4 = u & 3;
        const float4* src = (const float4*)(Af + (size_t)(row0 + row) * pitch + kof + c4 * 8);
        st[2*i]   = src[0];
        st[2*i+1] = src[1];
    }
}

template <bool LO>
__device__ __forceinline__ void conv_sts(const float4* st, uint32_t sdst, int tid)
{
#pragma unroll
    for (int i = 0; i < 2; ++i) {
        int u = tid + i * 256;
        int row = u >> 2;
        int c4 = u & 3;
        float f[8] = { st[2*i].x, st[2*i].y, st[2*i].z, st[2*i].w,
                       st[2*i+1].x, st[2*i+1].y, st[2*i+1].z, st[2*i+1].w };
        uint32_t hw[4], lw[4];
#pragma unroll
        for (int p = 0; p < 4; ++p) split2pack(f[2*p], f[2*p+1], hw[p], lw[p]);
        uint32_t base = sdst + row * 128;
        STS128(base + ((c4 ^ (row & 7)) << 4), hw[0], hw[1], hw[2], hw[3]);
        if (LO)
            STS128(base + (((c4 + 4) ^ (row & 7)) << 4), lw[0], lw[1], lw[2], lw[3]);
    }
}

template <int MODE, int TERMS, bool CONVA>
__global__ __launch_bounds__(256, 2) void mma_gemm(
    const float* __restrict__ Af,
    const __half* __restrict__ Ah, const __half* __restrict__ Al,
    const __half* __restrict__ Bh, const __half* __restrict__ Bl,
    const float* __restrict__ bias,
    float* __restrict__ Cf, __half* __restrict__ Chi, __half* __restrict__ Clo,
    int K, int ldc, size_t sA, size_t sB, size_t sC, int rbatch)
{
    extern __shared__ char smem[];
    const uint32_t sbase = smem_u32(smem);
    const int tid  = threadIdx.x;
    const int lane = tid & 31;
    const int wid  = tid >> 5;
    const int mw   = wid & 3;
    const int nw   = wid >> 2;
    const int m0 = blockIdx.y * 128;
    const int n0 = blockIdx.x * 128;
    const size_t z = blockIdx.z;
    if (CONVA) { Af += z * sA; } else { Ah += z * sA; Al += z * sA; }
    Bh += z * sB; Bl += z * sB;

    float c[2][8][4];
#pragma unroll
    for (int i = 0; i < 2; ++i)
#pragma unroll
        for (int j = 0; j < 8; ++j)
#pragma unroll
            for (int e = 0; e < 4; ++e) c[i][j][e] = 0.f;

    const int KS = K >> 5;

    // prologue: slab 0
    if (CONVA) {
        float4 st0[4];
        conv_ldg(Af, m0, 0, K, tid, st0);
        conv_sts<(TERMS == 3)>(st0, sbase + 0, tid);
    } else {
        cp_tile2<(TERMS == 3)>(Ah, Al, m0, 0, K, sbase + 0, tid);
    }
    cp_tile2<(TERMS >= 2)>(Bh, Bl, n0, 0, K, sbase + 16384, tid);
    CP_COMMIT();

    const int a_r = lane & 15;
    const int a_c = lane >> 4;
    const int b_r = ((lane >> 4) << 3) + (lane & 7);
    const int b_c = (lane >> 3) & 1;

    for (int s = 0; s < KS; ++s) {
        const uint32_t sb = sbase + (s & 1) * STG_BYTES;
        const uint32_t nb = sbase + ((s + 1) & 1) * STG_BYTES;
        const bool has_next = (s + 1 < KS);
        float4 st[4];
        if (has_next) {
            const int kof = (s + 1) * 32;
            if (CONVA) conv_ldg(Af, m0, kof, K, tid, st);
            else       cp_tile2<(TERMS == 3)>(Ah, Al, m0, kof, K, nb + 0, tid);
            cp_tile2<(TERMS >= 2)>(Bh, Bl, n0, kof, K, nb + 16384, tid);
            CP_COMMIT();
            CP_WAIT1();
        } else {
            CP_WAIT0();
        }
        __syncthreads();

#pragma unroll
        for (int kk = 0; kk < 2; ++kk) {
            uint32_t a_h[2][4], a_l[2][4];
#pragma unroll
            for (int mi = 0; mi < 2; ++mi) {
                const int row = mw * 32 + mi * 16 + a_r;
                const int ch = kk * 2 + a_c;
                const uint32_t base = sb + row * 128;
                LDMX4(a_h[mi], base + ((ch ^ (row & 7)) << 4));
                if (TERMS == 3) LDMX4(a_l[mi], base + (((ch + 4) ^ (row & 7)) << 4));
            }
#pragma unroll
            for (int np = 0; np < 4; ++np) {
                const int n = nw * 64 + np * 16 + b_r;
                const int ch = kk * 2 + b_c;
                const uint32_t base = sb + 16384 + n * 128;
                uint32_t bhf[4], blf[4];
                LDMX4(bhf, base + ((ch ^ (n & 7)) << 4));
                if (TERMS >= 2) LDMX4(blf, base + (((ch + 4) ^ (n & 7)) << 4));
#pragma unroll
                for (int mi = 0; mi < 2; ++mi) {
                    MMA16816(c[mi][2*np+0], a_h[mi], &bhf[0]);
                    if (TERMS >= 2) MMA16816(c[mi][2*np+0], a_h[mi], &blf[0]);
                    if (TERMS == 3) MMA16816(c[mi][2*np+0], a_l[mi], &bhf[0]);
                    MMA16816(c[mi][2*np+1], a_h[mi], &bhf[2]);
                    if (TERMS >= 2) MMA16816(c[mi][2*np+1], a_h[mi], &blf[2]);
                    if (TERMS == 3) MMA16816(c[mi][2*np+1], a_l[mi], &bhf[2]);
                }
            }
        }
        if (CONVA && has_next) conv_sts<(TERMS == 3)>(st, nb + 0, tid);
        __syncthreads();
    }

    // ---- epilogue ----
    if (MODE == 2) {
        float (*T)[129] = (float(*)[129])smem;
        const int rl0 = mw * 32 + (lane >> 2);
        const int cl0 = nw * 64 + (lane & 3) * 2;
#pragma unroll
        for (int mi = 0; mi < 2; ++mi)
#pragma unroll
            for (int hf = 0; hf < 2; ++hf) {
                const int rl = rl0 + mi * 16 + hf * 8;
#pragma unroll
                for (int nj = 0; nj < 8; ++nj) {
                    const int cl = cl0 + nj * 8;
                    float v0 = c[mi][nj][hf * 2 + 0] * INV_SQ;
                    float v1 = c[mi][nj][hf * 2 + 1] * INV_SQ;
                    if (bias) { v0 += __ldg(&bias[n0 + cl]); v1 += __ldg(&bias[n0 + cl + 1]); }
                    T[rl][cl]     = v0;
                    T[rl][cl + 1] = v1;
                }
            }
        __syncthreads();
        const int f  = tid >> 1;
        const int t0 = (tid & 1) * 64;
        const int b   = m0 / rbatch;
        const int r0l = m0 % rbatch;
        __half* dh = Chi + (size_t)b * sC + (size_t)(n0 + f) * ldc + r0l + t0;
        __half* dl = Clo + (size_t)b * sC + (size_t)(n0 + f) * ldc + r0l + t0;
#pragma unroll
        for (int q = 0; q < 8; ++q) {
            uint32_t hw[4], lw[4];
#pragma unroll
            for (int p = 0; p < 4; ++p) {
                float f0 = T[t0 + q * 8 + 2 * p][f];
                float f1 = T[t0 + q * 8 + 2 * p + 1][f];
                split2pack(f0, f1, hw[p], lw[p]);
            }
            ((uint4*)(dh + q * 8))[0] = make_uint4(hw[0], hw[1], hw[2], hw[3]);
            ((uint4*)(dl + q * 8))[0] = make_uint4(lw[0], lw[1], lw[2], lw[3]);
        }
        return;
    }

    const int r_base = m0 + mw * 32 + (lane >> 2);
    const int c_base = n0 + nw * 64 + (lane & 3) * 2;
#pragma unroll
    for (int mi = 0; mi < 2; ++mi) {
#pragma unroll
        for (int hf = 0; hf < 2; ++hf) {
            const size_t row = (size_t)(r_base + mi * 16 + hf * 8);
#pragma unroll
            for (int nj = 0; nj < 8; ++nj) {
                const int col = c_base + nj * 8;
                float v0 = c[mi][nj][hf * 2 + 0] * INV_SQ;
                float v1 = c[mi][nj][hf * 2 + 1] * INV_SQ;
                if (bias) { v0 += __ldg(&bias[col]); v1 += __ldg(&bias[col + 1]); }
                if (MODE == 0) {
                    float2* dst = (float2*)(Cf + z * sC + row * ldc + col);
                    *dst = make_float2(v0, v1);
                } else {
                    uint32_t hw, lw;
                    split2pack(v0, v1, hw, lw);
                    *(uint32_t*)(Chi + z * sC + row * ldc + col) = hw;
                    *(uint32_t*)(Clo + z * sC + row * ldc + col) = lw;
                }
            }
        }
    }
}

// ------------------------------ aux kernels ---------------------------------
// dst[c][r] = split(src[r][c]); src [R,C] fp32, dst [C,R] fp16 hi/lo.
__global__ __launch_bounds__(256) void tsplit_kernel(
    const float* __restrict__ src, __half* __restrict__ dh,
    __half* __restrict__ dl, int R, int C, size_t sS, size_t sD)
{
    __shared__ float t[32][33];
    const size_t z = blockIdx.z;
    src += z * sS; dh += z * sD; dl += z * sD;
    const int c0 = blockIdx.x * 32, r0 = blockIdx.y * 32;
    const int tx = threadIdx.x, ty = threadIdx.y;
#pragma unroll
    for (int k = 0; k < 4; ++k)
        t[ty + 8*k][tx] = src[(size_t)(r0 + ty + 8*k) * C + c0 + tx];
    __syncthreads();
#pragma unroll
    for (int k = 0; k < 4; ++k) {
        float f = t[tx][ty + 8*k] * SCALE_F;
        __half h = __float2half_rn(f);
        size_t o = (size_t)(c0 + ty + 8*k) * R + r0 + tx;
        dh[o] = h;
        dl[o] = __float2half_rn(f - __half2float(h));
    }
}

// bvo[f] = sum_c bv[c] * Wo[c][f]
__global__ __launch_bounds__(256) void bvo_kernel(
    const float* __restrict__ bv, const float* __restrict__ wo,
    float* __restrict__ bvo)
{
    int f = blockIdx.x * 256 + threadIdx.x;
    float s = 0.f;
    for (int c = 0; c < CH; ++c) s = fmaf(bv[c], wo[(size_t)c * CH + f], s);
    bvo[f] = s;
}

__global__ __launch_bounds__(256) void softmax_mask_split_kernel(
    const float* __restrict__ S, const float* __restrict__ masks,
    float* __restrict__ beta, __half* __restrict__ bh,
    __half* __restrict__ bl)
{
    const int row = blockIdx.x;
    const int b = row >> 8;
    const int n = threadIdx.x;
    __shared__ float red[256];

    const size_t idx = (size_t)row * NTOK + n;
    float v = S[idx];
    red[n] = v;
    __syncthreads();
#pragma unroll
    for (int s = 128; s > 0; s >>= 1) {
        if (n < s) red[n] = fmaxf(red[n], red[n + s]);
        __syncthreads();
    }
    const float mx = red[0];
    __syncthreads();
    const float e = expf(v - mx);
    red[n] = e;
    __syncthreads();
#pragma unroll
    for (int s = 128; s > 0; s >>= 1) {
        if (n < s) red[n] += red[n + s];
        __syncthreads();
    }
    const float r = e / red[0] * masks[b * NTOK + n];
    beta[idx] = r;
    const float rs = r * SCALE_F;
    __half h = __float2half_rn(rs);
    bh[idx] = h;
    bl[idx] = __float2half_rn(rs - __half2float(h));
}

// ------------------------------ host ----------------------------------------
extern "C" void kernel_launch(void* const* d_in, const int* in_sizes, int n_in,
                              void* d_out, int out_size) {
    const float* x1    = (const float*)d_in[0];
    const float* x2    = (const float*)d_in[1];
    const float* masks = (const float*)d_in[2];
    const float* wq    = (const float*)d_in[3];
    const float* bq    = (const float*)d_in[4];
    const float* wk    = (const float*)d_in[5];
    const float* bk    = (const float*)d_in[6];
    const float* wv    = (const float*)d_in[7];
    const float* bv    = (const float*)d_in[8];
    const float* wo    = (const float*)d_in[9];
    const float* bo    = (const float*)d_in[10];

    float* out      = (float*)d_out;
    float* o_out    = out;
    float* beta_out = out + (size_t)MROWS * CH;

    __half *wqh, *wql, *wkh, *wkl, *woh, *wol, *Qh, *Ql, *Kh, *Kl,
           *Wvoth, *Wvotl, *VWth, *VWtl, *bh, *bl;
    float *bvo, *Sf;
    cudaGetSymbolAddress((void**)&wqh, g_wqh); cudaGetSymbolAddress((void**)&wql, g_wql);
    cudaGetSymbolAddress((void**)&wkh, g_wkh); cudaGetSymbolAddress((void**)&wkl, g_wkl);
    cudaGetSymbolAddress((void**)&woh, g_woh); cudaGetSymbolAddress((void**)&wol, g_wol);
    cudaGetSymbolAddress((void**)&Qh,  g_Qh);  cudaGetSymbolAddress((void**)&Ql,  g_Ql);
    cudaGetSymbolAddress((void**)&Kh,  g_Kh);  cudaGetSymbolAddress((void**)&Kl,  g_Kl);
    cudaGetSymbolAddress((void**)&bvo, g_bvo);
    cudaGetSymbolAddress((void**)&Wvoth, g_Wvoth); cudaGetSymbolAddress((void**)&Wvotl, g_Wvotl);
    cudaGetSymbolAddress((void**)&VWth, g_VWth); cudaGetSymbolAddress((void**)&VWtl, g_VWtl);
    cudaGetSymbolAddress((void**)&Sf,  g_S);
    cudaGetSymbolAddress((void**)&bh,  g_bh);  cudaGetSymbolAddress((void**)&bl,  g_bl);

    cudaFuncSetAttribute((const void*)mma_gemm<1,3,true>,  cudaFuncAttributeMaxDynamicSharedMemorySize, SMEM_BYTES);
    cudaFuncSetAttribute((const void*)mma_gemm<2,1,true>,  cudaFuncAttributeMaxDynamicSharedMemorySize, SMEM_BYTES_T);
    cudaFuncSetAttribute((const void*)mma_gemm<0,3,false>, cudaFuncAttributeMaxDynamicSharedMemorySize, SMEM_BYTES);
    cudaFuncSetAttribute((const void*)mma_gemm<0,1,false>, cudaFuncAttributeMaxDynamicSharedMemorySize, SMEM_BYTES);

    const dim3 T(256);
    const dim3 TT(32, 8);

    // weight prep (B-side splits only; A-side conversions fused into GEMMs)
    tsplit_kernel<<<dim3(FD/32, CH/32, 1), TT>>>(wq, wqh, wql, CH, FD, 0, 0);
    tsplit_kernel<<<dim3(FD/32, TC/32, 1), TT>>>(wk, wkh, wkl, TC, FD, 0, 0);
    tsplit_kernel<<<dim3(CH/32, CH/32, 1), TT>>>(wo, woh, wol, CH, CH, 0, 0);
    bvo_kernel<<<CH/256, 256>>>(bv, wo, bvo);

    // Wvo = Wv @ Wo  -> transposed hi/lo  (1-term, A = wv fp32 fused-convert)
    mma_gemm<2,1,true><<<dim3(CH/128, TC/128, 1), T, SMEM_BYTES_T>>>(
        wv, nullptr, nullptr, woh, wol, nullptr, nullptr, Wvoth, Wvotl,
        CH, TC, 0, 0, 0, TC);

    // Q = x1 @ Wq + bq  -> hi/lo  (3-term, A = x1 fp32 fused-convert)
    mma_gemm<1,3,true><<<dim3(FD/128, MROWS/128, 1), T, SMEM_BYTES>>>(
        x1, nullptr, nullptr, wqh, wql, bq, nullptr, Qh, Ql, CH, FD, 0, 0, 0, 1);
    // K = x2 @ Wk + bk  -> hi/lo  (3-term, A = x2 fp32 fused-convert)
    mma_gemm<1,3,true><<<dim3(FD/128, MROWS/128, 1), T, SMEM_BYTES>>>(
        x2, nullptr, nullptr, wkh, wkl, bk, nullptr, Kh, Kl, TC, FD, 0, 0, 0, 1);

    // VW = x2 @ Wvo + bvo -> per-batch transposed hi/lo  (1-term, fused-convert)
    mma_gemm<2,1,true><<<dim3(CH/128, MROWS/128, 1), T, SMEM_BYTES_T>>>(
        x2, nullptr, nullptr, Wvoth, Wvotl, bvo, nullptr, VWth, VWtl,
        TC, NTOK, 0, 0, (size_t)CH*NTOK, NTOK);

    // S[b] = Q_b @ K_b^T -> fp32  (3-term)
    mma_gemm<0,3,false><<<dim3(NTOK/128, HW/128, BATCH), T, SMEM_BYTES>>>(
        nullptr, Qh, Ql, Kh, Kl, nullptr, Sf, nullptr, nullptr, FD, NTOK,
        (size_t)HW*FD, (size_t)NTOK*FD, (size_t)HW*NTOK, 1);

    // beta = softmax(S) * mask -> d_out + hi/lo
    softmax_mask_split_kernel<<<MROWS, 256>>>(Sf, masks, beta_out, bh, bl);

    // o[b] = beta_b @ VW_b + bo -> fp32 out  (1-term)
    mma_gemm<0,1,false><<<dim3(CH/128, HW/128, BATCH), T, SMEM_BYTES>>>(
        nullptr, bh, bl, VWth, VWtl, bo, o_out, nullptr, nullptr, NTOK, CH,
        (size_t)HW*NTOK, (size_t)CH*NTOK, (size_t)HW*CH, 1);
}

// round 17
// speedup vs baseline: 1.1600x; 1.1600x over previous
#include <cuda_runtime.h>
#include <cuda_fp16.h>
#include <cstdint>
#include <cstddef>

#define BATCH 64
#define HW    256
#define CH    1024
#define NTOK  256
#define TC    768
#define FD    512
#define MROWS (BATCH*HW)   // 16384

#define SCALE_F   256.0f
#define INV_SQ    (1.0f/65536.0f)

// ------------------------------ scratch (device globals; no allocs) ---------
__device__ __align__(256) __half g_x1h[(size_t)MROWS*CH], g_x1l[(size_t)MROWS*CH];
__device__ __align__(256) __half g_x2h[(size_t)MROWS*TC], g_x2l[(size_t)MROWS*TC];
__device__ __align__(256) __half g_wqh[(size_t)FD*CH],  g_wql[(size_t)FD*CH];
__device__ __align__(256) __half g_wkh[(size_t)FD*TC],  g_wkl[(size_t)FD*TC];
__device__ __align__(256) __half g_wvh[(size_t)TC*CH],  g_wvl[(size_t)TC*CH];
__device__ __align__(256) __half g_woh[(size_t)CH*CH],  g_wol[(size_t)CH*CH];   // Wo^T [f,c]
__device__ __align__(256) __half g_Qh[(size_t)MROWS*FD], g_Ql[(size_t)MROWS*FD];
__device__ __align__(256) __half g_Kh[(size_t)MROWS*FD], g_Kl[(size_t)MROWS*FD];
__device__ __align__(256) float  g_bvo_part[16*CH];
__device__ __align__(256) float  g_bvo[CH];
__device__ __align__(256) __half g_Wvoth[(size_t)CH*TC], g_Wvotl[(size_t)CH*TC];// (Wv@Wo)^T hi/lo
__device__ __align__(256) __half g_VWth[(size_t)MROWS*CH], g_VWtl[(size_t)MROWS*CH]; // [b][CH][NTOK]
__device__ __align__(256) float  g_S [(size_t)MROWS*NTOK];
__device__ __align__(256) __half g_bh[(size_t)MROWS*NTOK], g_bl[(size_t)MROWS*NTOK];

// ------------------------------ PTX helpers ---------------------------------
__device__ __forceinline__ uint32_t smem_u32(const void* p) {
    uint32_t a;
    asm("{ .reg .u64 t; cvta.to.shared.u64 t, %1; cvt.u32.u64 %0, t; }" : "=r"(a) : "l"(p));
    return a;
}
#define CP_ASYNC16(dst, src) \
    asm volatile("cp.async.cg.shared.global [%0], [%1], 16;" :: "r"(dst), "l"(src))
#define CP_COMMIT() asm volatile("cp.async.commit_group;" ::: "memory")
#define CP_WAIT1()  asm volatile("cp.async.wait_group 1;" ::: "memory")
#define CP_WAIT0()  asm volatile("cp.async.wait_group 0;" ::: "memory")

#define LDMX4(r, addr)                                                      \
    asm volatile("ldmatrix.sync.aligned.m8n8.x4.shared.b16 {%0,%1,%2,%3}, [%4];" \
        : "=r"((r)[0]), "=r"((r)[1]), "=r"((r)[2]), "=r"((r)[3]) : "r"(addr))

#define MMA16816(c, a, b)                                                   \
    asm volatile("mma.sync.aligned.m16n8k16.row.col.f32.f16.f16.f32 "       \
        "{%0,%1,%2,%3}, {%4,%5,%6,%7}, {%8,%9}, {%0,%1,%2,%3};"             \
        : "+f"((c)[0]), "+f"((c)[1]), "+f"((c)[2]), "+f"((c)[3])            \
        : "r"((a)[0]), "r"((a)[1]), "r"((a)[2]), "r"((a)[3]),               \
          "r"((b)[0]), "r"((b)[1]))

// split f -> fp16 hi/lo of (f*256), packed pairs
__device__ __forceinline__ void split2pack(float f0, float f1, uint32_t& hw, uint32_t& lw) {
    float s0 = f0 * SCALE_F, s1 = f1 * SCALE_F;
    __half h0 = __float2half_rn(s0);
    __half h1 = __float2half_rn(s1);
    __half l0 = __float2half_rn(s0 - __half2float(h0));
    __half l1 = __float2half_rn(s1 - __half2float(h1));
    hw = (uint32_t)__half_as_ushort(h0) | ((uint32_t)__half_as_ushort(h1) << 16);
    lw = (uint32_t)__half_as_ushort(l0) | ((uint32_t)__half_as_ushort(l1) << 16);
}

// ------------------------------ GEMM (R14 config) ---------------------------
// Operands are fp16 hi/lo splits of (X*256); accumulator holds 65536*true.
// TERMS==3: AhBh + AhBl + AlBh.   TERMS==1: AhBh only (lo never loaded).
// MODE 0: fp32 row-major C.  MODE 1: fp16 hi/lo row-major C.
// MODE 2: fp16 hi/lo TRANSPOSED C via smem; ldc = out pitch, sC = batch stride,
//         rbatch = source rows per batch.
#define STG_BYTES 32768
#define SMEM_BYTES (2*STG_BYTES)
#define SMEM_BYTES_T (128*129*4)

template <bool LO>
__device__ __forceinline__ void cp_tile2(
    const __half* __restrict__ gh, const __half* __restrict__ gl,
    int row0, int kof, int pitch, uint32_t sdst, int tid)
{
#pragma unroll
    for (int i = 0; i < 2; ++i) {
        int u = tid + i * 256;
        int row = u >> 2;
        int c4 = u & 3;
        {
            int c = c4;
            uint32_t dst = sdst + row * 128 + ((c ^ (row & 7)) << 4);
            const void* src = gh + (size_t)(row0 + row) * pitch + kof + c4 * 8;
            CP_ASYNC16(dst, src);
        }
        if (LO) {
            int c = c4 + 4;
            uint32_t dst = sdst + row * 128 + ((c ^ (row & 7)) << 4);
            const void* src = gl + (size_t)(row0 + row) * pitch + kof + c4 * 8;
            CP_ASYNC16(dst, src);
        }
    }
}

template <int MODE, int TERMS>
__global__ __launch_bounds__(256, 2) void mma_gemm(
    const __half* __restrict__ Ah, const __half* __restrict__ Al,
    const __half* __restrict__ Bh, const __half* __restrict__ Bl,
    const float* __restrict__ bias,
    float* __restrict__ Cf, __half* __restrict__ Chi, __half* __restrict__ Clo,
    int K, int ldc, size_t sA, size_t sB, size_t sC, int rbatch)
{
    extern __shared__ char smem[];
    const uint32_t sbase = smem_u32(smem);
    const int tid  = threadIdx.x;
    const int lane = tid & 31;
    const int wid  = tid >> 5;
    const int mw   = wid & 3;
    const int nw   = wid >> 2;
    const int m0 = blockIdx.y * 128;
    const int n0 = blockIdx.x * 128;
    const size_t z = blockIdx.z;
    Ah += z * sA; Al += z * sA;
    Bh += z * sB; Bl += z * sB;

    float c[2][8][4];
#pragma unroll
    for (int i = 0; i < 2; ++i)
#pragma unroll
        for (int j = 0; j < 8; ++j)
#pragma unroll
            for (int e = 0; e < 4; ++e) c[i][j][e] = 0.f;

    const int KS = K >> 5;

    cp_tile2<(TERMS == 3)>(Ah, Al, m0, 0, K, sbase + 0,     tid);
    cp_tile2<(TERMS >= 2)>(Bh, Bl, n0, 0, K, sbase + 16384, tid);
    CP_COMMIT();

    const int a_r = lane & 15;
    const int a_c = lane >> 4;
    const int b_r = ((lane >> 4) << 3) + (lane & 7);
    const int b_c = (lane >> 3) & 1;

    for (int s = 0; s < KS; ++s) {
        const uint32_t sb = sbase + (s & 1) * STG_BYTES;
        if (s + 1 < KS) {
            const uint32_t nb = sbase + ((s + 1) & 1) * STG_BYTES;
            const int kof = (s + 1) * 32;
            cp_tile2<(TERMS == 3)>(Ah, Al, m0, kof, K, nb + 0,     tid);
            cp_tile2<(TERMS >= 2)>(Bh, Bl, n0, kof, K, nb + 16384, tid);
            CP_COMMIT();
            CP_WAIT1();
        } else {
            CP_WAIT0();
        }
        __syncthreads();

#pragma unroll
        for (int kk = 0; kk < 2; ++kk) {
            uint32_t a_h[2][4], a_l[2][4];
#pragma unroll
            for (int mi = 0; mi < 2; ++mi) {
                const int row = mw * 32 + mi * 16 + a_r;
                const int ch = kk * 2 + a_c;
                const uint32_t base = sb + row * 128;
                LDMX4(a_h[mi], base + ((ch ^ (row & 7)) << 4));
                if (TERMS == 3) LDMX4(a_l[mi], base + (((ch + 4) ^ (row & 7)) << 4));
            }
#pragma unroll
            for (int np = 0; np < 4; ++np) {
                const int n = nw * 64 + np * 16 + b_r;
                const int ch = kk * 2 + b_c;
                const uint32_t base = sb + 16384 + n * 128;
                uint32_t bhf[4], blf[4];
                LDMX4(bhf, base + ((ch ^ (n & 7)) << 4));
                if (TERMS >= 2) LDMX4(blf, base + (((ch + 4) ^ (n & 7)) << 4));
#pragma unroll
                for (int mi = 0; mi < 2; ++mi) {
                    MMA16816(c[mi][2*np+0], a_h[mi], &bhf[0]);
                    if (TERMS >= 2) MMA16816(c[mi][2*np+0], a_h[mi], &blf[0]);
                    if (TERMS == 3) MMA16816(c[mi][2*np+0], a_l[mi], &bhf[0]);
                    MMA16816(c[mi][2*np+1], a_h[mi], &bhf[2]);
                    if (TERMS >= 2) MMA16816(c[mi][2*np+1], a_h[mi], &blf[2]);
                    if (TERMS == 3) MMA16816(c[mi][2*np+1], a_l[mi], &bhf[2]);
                }
            }
        }
        __syncthreads();
    }

    // ---- epilogue ----
    if (MODE == 2) {
        float (*T)[129] = (float(*)[129])smem;
        const int rl0 = mw * 32 + (lane >> 2);
        const int cl0 = nw * 64 + (lane & 3) * 2;
#pragma unroll
        for (int mi = 0; mi < 2; ++mi)
#pragma unroll
            for (int hf = 0; hf < 2; ++hf) {
                const int rl = rl0 + mi * 16 + hf * 8;
#pragma unroll
                for (int nj = 0; nj < 8; ++nj) {
                    const int cl = cl0 + nj * 8;
                    float v0 = c[mi][nj][hf * 2 + 0] * INV_SQ;
                    float v1 = c[mi][nj][hf * 2 + 1] * INV_SQ;
                    if (bias) { v0 += __ldg(&bias[n0 + cl]); v1 += __ldg(&bias[n0 + cl + 1]); }
                    T[rl][cl]     = v0;
                    T[rl][cl + 1] = v1;
                }
            }
        __syncthreads();
        const int f  = tid >> 1;
        const int t0 = (tid & 1) * 64;
        const int b   = m0 / rbatch;
        const int r0l = m0 % rbatch;
        __half* dh = Chi + (size_t)b * sC + (size_t)(n0 + f) * ldc + r0l + t0;
        __half* dl = Clo + (size_t)b * sC + (size_t)(n0 + f) * ldc + r0l + t0;
#pragma unroll
        for (int q = 0; q < 8; ++q) {
            uint32_t hw[4], lw[4];
#pragma unroll
            for (int p = 0; p < 4; ++p) {
                float f0 = T[t0 + q * 8 + 2 * p][f];
                float f1 = T[t0 + q * 8 + 2 * p + 1][f];
                split2pack(f0, f1, hw[p], lw[p]);
            }
            ((uint4*)(dh + q * 8))[0] = make_uint4(hw[0], hw[1], hw[2], hw[3]);
            ((uint4*)(dl + q * 8))[0] = make_uint4(lw[0], lw[1], lw[2], lw[3]);
        }
        return;
    }

    const int r_base = m0 + mw * 32 + (lane >> 2);
    const int c_base = n0 + nw * 64 + (lane & 3) * 2;
#pragma unroll
    for (int mi = 0; mi < 2; ++mi) {
#pragma unroll
        for (int hf = 0; hf < 2; ++hf) {
            const size_t row = (size_t)(r_base + mi * 16 + hf * 8);
#pragma unroll
            for (int nj = 0; nj < 8; ++nj) {
                const int col = c_base + nj * 8;
                float v0 = c[mi][nj][hf * 2 + 0] * INV_SQ;
                float v1 = c[mi][nj][hf * 2 + 1] * INV_SQ;
                if (bias) { v0 += __ldg(&bias[col]); v1 += __ldg(&bias[col + 1]); }
                if (MODE == 0) {
                    float2* dst = (float2*)(Cf + z * sC + row * ldc + col);
                    *dst = make_float2(v0, v1);
                } else {
                    uint32_t hw, lw;
                    split2pack(v0, v1, hw, lw);
                    *(uint32_t*)(Chi + z * sC + row * ldc + col) = hw;
                    *(uint32_t*)(Clo + z * sC + row * ldc + col) = lw;
                }
            }
        }
    }
}

// ------------------------------ aux kernels ---------------------------------
__global__ __launch_bounds__(256) void split_kernel(
    const float4* __restrict__ src, __half* __restrict__ dh,
    __half* __restrict__ dl, int n4)
{
    int i = blockIdx.x * 256 + threadIdx.x;
    if (i >= n4) return;
    float4 v = src[i];
    uint32_t hw0, lw0, hw1, lw1;
    split2pack(v.x, v.y, hw0, lw0);
    split2pack(v.z, v.w, hw1, lw1);
    ((uint2*)dh)[i] = make_uint2(hw0, hw1);
    ((uint2*)dl)[i] = make_uint2(lw0, lw1);
}

// dst[c][r] = split(src[r][c]); src [R,C] fp32, dst [C,R] fp16 hi/lo.
__global__ __launch_bounds__(256) void tsplit_kernel(
    const float* __restrict__ src, __half* __restrict__ dh,
    __half* __restrict__ dl, int R, int C, size_t sS, size_t sD)
{
    __shared__ float t[32][33];
    const size_t z = blockIdx.z;
    src += z * sS; dh += z * sD; dl += z * sD;
    const int c0 = blockIdx.x * 32, r0 = blockIdx.y * 32;
    const int tx = threadIdx.x, ty = threadIdx.y;
#pragma unroll
    for (int k = 0; k < 4; ++k)
        t[ty + 8*k][tx] = src[(size_t)(r0 + ty + 8*k) * C + c0 + tx];
    __syncthreads();
#pragma unroll
    for (int k = 0; k < 4; ++k) {
        float f = t[tx][ty + 8*k] * SCALE_F;
        __half h = __float2half_rn(f);
        size_t o = (size_t)(c0 + ty + 8*k) * R + r0 + tx;
        dh[o] = h;
        dl[o] = __float2half_rn(f - __half2float(h));
    }
}

// pass 1: partial[chunk][f] = sum over 64 c's of bv[c]*Wo[c][f]
__global__ __launch_bounds__(256) void bvo_part_kernel(
    const float* __restrict__ bv, const float* __restrict__ wo,
    float* __restrict__ part)
{
    int f = blockIdx.x * 256 + threadIdx.x;      // 0..1023 (grid.x = 4)
    int ch = blockIdx.y;                          // 0..15
    int c0 = ch * 64;
    float s = 0.f;
#pragma unroll 8
    for (int c = 0; c < 64; ++c)
        s = fmaf(bv[c0 + c], wo[(size_t)(c0 + c) * CH + f], s);
    part[ch * CH + f] = s;
}
// pass 2: bvo[f] = sum_chunk part[chunk][f]  (fixed order -> deterministic)
__global__ __launch_bounds__(256) void bvo_sum_kernel(
    const float* __restrict__ part, float* __restrict__ bvo)
{
    int f = blockIdx.x * 256 + threadIdx.x;
    float s = 0.f;
#pragma unroll
    for (int ch = 0; ch < 16; ++ch) s += part[ch * CH + f];
    bvo[f] = s;
}

__global__ __launch_bounds__(256) void softmax_mask_split_kernel(
    const float* __restrict__ S, const float* __restrict__ masks,
    float* __restrict__ beta, __half* __restrict__ bh,
    __half* __restrict__ bl)
{
    const int row = blockIdx.x;
    const int b = row >> 8;
    const int n = threadIdx.x;
    __shared__ float red[256];

    const size_t idx = (size_t)row * NTOK + n;
    float v = S[idx];
    red[n] = v;
    __syncthreads();
#pragma unroll
    for (int s = 128; s > 0; s >>= 1) {
        if (n < s) red[n] = fmaxf(red[n], red[n + s]);
        __syncthreads();
    }
    const float mx = red[0];
    __syncthreads();
    const float e = expf(v - mx);
    red[n] = e;
    __syncthreads();
#pragma unroll
    for (int s = 128; s > 0; s >>= 1) {
        if (n < s) red[n] += red[n + s];
        __syncthreads();
    }
    const float r = e / red[0] * masks[b * NTOK + n];
    beta[idx] = r;
    const float rs = r * SCALE_F;
    __half h = __float2half_rn(rs);
    bh[idx] = h;
    bl[idx] = __float2half_rn(rs - __half2float(h));
}

// ------------------------------ host ----------------------------------------
extern "C" void kernel_launch(void* const* d_in, const int* in_sizes, int n_in,
                              void* d_out, int out_size) {
    const float* x1    = (const float*)d_in[0];
    const float* x2    = (const float*)d_in[1];
    const float* masks = (const float*)d_in[2];
    const float* wq    = (const float*)d_in[3];
    const float* bq    = (const float*)d_in[4];
    const float* wk    = (const float*)d_in[5];
    const float* bk    = (const float*)d_in[6];
    const float* wv    = (const float*)d_in[7];
    const float* bv    = (const float*)d_in[8];
    const float* wo    = (const float*)d_in[9];
    const float* bo    = (const float*)d_in[10];

    float* out      = (float*)d_out;
    float* o_out    = out;
    float* beta_out = out + (size_t)MROWS * CH;

    __half *x1h, *x1l, *x2h, *x2l, *wqh, *wql, *wkh, *wkl, *wvh, *wvl,
           *woh, *wol, *Qh, *Ql, *Kh, *Kl, *Wvoth, *Wvotl, *VWth, *VWtl, *bh, *bl;
    float *bvo_part, *bvo, *Sf;
    cudaGetSymbolAddress((void**)&x1h, g_x1h); cudaGetSymbolAddress((void**)&x1l, g_x1l);
    cudaGetSymbolAddress((void**)&x2h, g_x2h); cudaGetSymbolAddress((void**)&x2l, g_x2l);
    cudaGetSymbolAddress((void**)&wqh, g_wqh); cudaGetSymbolAddress((void**)&wql, g_wql);
    cudaGetSymbolAddress((void**)&wkh, g_wkh); cudaGetSymbolAddress((void**)&wkl, g_wkl);
    cudaGetSymbolAddress((void**)&wvh, g_wvh); cudaGetSymbolAddress((void**)&wvl, g_wvl);
    cudaGetSymbolAddress((void**)&woh, g_woh); cudaGetSymbolAddress((void**)&wol, g_wol);
    cudaGetSymbolAddress((void**)&Qh,  g_Qh);  cudaGetSymbolAddress((void**)&Ql,  g_Ql);
    cudaGetSymbolAddress((void**)&Kh,  g_Kh);  cudaGetSymbolAddress((void**)&Kl,  g_Kl);
    cudaGetSymbolAddress((void**)&bvo_part, g_bvo_part);
    cudaGetSymbolAddress((void**)&bvo, g_bvo);
    cudaGetSymbolAddress((void**)&Wvoth, g_Wvoth); cudaGetSymbolAddress((void**)&Wvotl, g_Wvotl);
    cudaGetSymbolAddress((void**)&VWth, g_VWth); cudaGetSymbolAddress((void**)&VWtl, g_VWtl);
    cudaGetSymbolAddress((void**)&Sf,  g_S);
    cudaGetSymbolAddress((void**)&bh,  g_bh);  cudaGetSymbolAddress((void**)&bl,  g_bl);

    cudaFuncSetAttribute((const void*)mma_gemm<0,3>, cudaFuncAttributeMaxDynamicSharedMemorySize, SMEM_BYTES);
    cudaFuncSetAttribute((const void*)mma_gemm<1,3>, cudaFuncAttributeMaxDynamicSharedMemorySize, SMEM_BYTES);
    cudaFuncSetAttribute((const void*)mma_gemm<0,1>, cudaFuncAttributeMaxDynamicSharedMemorySize, SMEM_BYTES);
    cudaFuncSetAttribute((const void*)mma_gemm<2,1>, cudaFuncAttributeMaxDynamicSharedMemorySize, SMEM_BYTES_T);

    const dim3 T(256);
    const dim3 TT(32, 8);

    // splits / weight prep
    split_kernel<<<(MROWS*CH/4 + 255)/256, 256>>>((const float4*)x1, x1h, x1l, MROWS*CH/4);
    split_kernel<<<(MROWS*TC/4 + 255)/256, 256>>>((const float4*)x2, x2h, x2l, MROWS*TC/4);
    split_kernel<<<(TC*CH/4 + 255)/256, 256>>>((const float4*)wv, wvh, wvl, TC*CH/4);
    tsplit_kernel<<<dim3(FD/32, CH/32, 1), TT>>>(wq, wqh, wql, CH, FD, 0, 0);
    tsplit_kernel<<<dim3(FD/32, TC/32, 1), TT>>>(wk, wkh, wkl, TC, FD, 0, 0);
    tsplit_kernel<<<dim3(CH/32, CH/32, 1), TT>>>(wo, woh, wol, CH, CH, 0, 0);
    bvo_part_kernel<<<dim3(CH/256, 16), 256>>>(bv, wo, bvo_part);
    bvo_sum_kernel<<<CH/256, 256>>>(bvo_part, bvo);

    // Wvo = Wv @ Wo  -> transposed hi/lo  (M=768, N=1024, K=1024), 1-term
    mma_gemm<2,1><<<dim3(CH/128, TC/128, 1), T, SMEM_BYTES_T>>>(
        wvh, wvl, woh, wol, nullptr, nullptr, Wvoth, Wvotl, CH, TC, 0, 0, 0, TC);

    // Q = x1 @ Wq + bq  -> hi/lo   (3-term)
    mma_gemm<1,3><<<dim3(FD/128, MROWS/128, 1), T, SMEM_BYTES>>>(
        x1h, x1l, wqh, wql, bq, nullptr, Qh, Ql, CH, FD, 0, 0, 0, 1);
    // K = x2 @ Wk + bk  -> hi/lo   (3-term)
    mma_gemm<1,3><<<dim3(FD/128, MROWS/128, 1), T, SMEM_BYTES>>>(
        x2h, x2l, wkh, wkl, bk, nullptr, Kh, Kl, TC, FD, 0, 0, 0, 1);

    // VW = x2 @ Wvo + bvo -> per-batch transposed hi/lo  (1-term)
    mma_gemm<2,1><<<dim3(CH/128, MROWS/128, 1), T, SMEM_BYTES_T>>>(
        x2h, x2l, Wvoth, Wvotl, bvo, nullptr, VWth, VWtl, TC, NTOK,
        0, 0, (size_t)CH*NTOK, NTOK);

    // S[b] = Q_b @ K_b^T -> fp32   (3-term)
    mma_gemm<0,3><<<dim3(NTOK/128, HW/128, BATCH), T, SMEM_BYTES>>>(
        Qh, Ql, Kh, Kl, nullptr, Sf, nullptr, nullptr, FD, NTOK,
        (size_t)HW*FD, (size_t)NTOK*FD, (size_t)HW*NTOK, 1);

    // beta = softmax(S) * mask -> d_out + hi/lo
    softmax_mask_split_kernel<<<MROWS, 256>>>(Sf, masks, beta_out, bh, bl);

    // o[b] = beta_b @ VW_b + bo -> fp32 out   (1-term)
    mma_gemm<0,1><<<dim3(CH/128, HW/128, BATCH), T, SMEM_BYTES>>>(
        bh, bl, VWth, VWtl, bo, o_out, nullptr, nullptr, NTOK, CH,
        (size_t)HW*NTOK, (size_t)CH*NTOK, (size_t)HW*CH, 1);
}